// round 14
// baseline (speedup 1.0000x reference)
#include <cuda_runtime.h>
#include <cstdint>

#define B 64
#define C 256
#define CS 64
#define NC 8
#define BC (B * C)   // 16384

// Scratch (device globals: no allocation allowed)
__device__ float g_sum[BC];
__device__ float g_min[BC];
__device__ float g_max[BC];
__device__ float g_scale[BC];
__device__ float g_smin[B];
__device__ float g_smax[B];

// ---------------------------------------------------------------------------
// Kernel 1: per-(b,c) sum / min / max over 4096 spatial elements.
// One WARP per (b,c) row; 2048 blocks x 256 threads. Plain launch boundary
// after it (PDL here measurably steals its DRAM bandwidth - R6).
// ---------------------------------------------------------------------------
__global__ __launch_bounds__(256) void reduce_kernel(const float* __restrict__ x) {
    const int w = threadIdx.x >> 5;
    const int lane = threadIdx.x & 31;
    const int bc = (blockIdx.x << 3) + w;
    const float4* p = reinterpret_cast<const float4*>(x) + (size_t)bc * 1024;

    float s = 0.0f, mn = 3.4028235e38f, mx = -3.4028235e38f;
#pragma unroll 8
    for (int k = 0; k < 32; ++k) {
        float4 v = __ldcg(&p[lane + (k << 5)]);
        s += (v.x + v.y) + (v.z + v.w);
        mn = fminf(mn, fminf(fminf(v.x, v.y), fminf(v.z, v.w)));
        mx = fmaxf(mx, fmaxf(fmaxf(v.x, v.y), fmaxf(v.z, v.w)));
    }
#pragma unroll
    for (int o = 16; o; o >>= 1) {
        s += __shfl_xor_sync(0xFFFFFFFFu, s, o);
        mn = fminf(mn, __shfl_xor_sync(0xFFFFFFFFu, mn, o));
        mx = fmaxf(mx, __shfl_xor_sync(0xFFFFFFFFu, mx, o));
    }
    if (lane == 0) {
        g_sum[bc] = s;
        g_min[bc] = mn;
        g_max[bc] = mx;
    }
}

// ---------------------------------------------------------------------------
// Kernel 2: per-sample SE MLP + scale + per-sample min/max of (scale * x).
// 64 blocks x 256 threads. Triggers dependent (quant) launch at ENTRY:
// quant's first wave prefetches x during se's ~3us runtime (84 idle SMs).
// ---------------------------------------------------------------------------
__global__ __launch_bounds__(256) void se_kernel(const float* __restrict__ w1,
                                                 const float* __restrict__ b1,
                                                 const float* __restrict__ w2,
                                                 const float* __restrict__ b2) {
    asm volatile("griddepcontrol.launch_dependents;" ::: "memory");
    const int b = blockIdx.x;
    const int t = threadIdx.x;
    const int w = t >> 5, lane = t & 31;

    __shared__ __align__(16) float sp[C];
    __shared__ __align__(16) float sh_[CS];
    __shared__ float rmn[8], rmx[8];

    sp[t] = g_sum[b * C + t] * (1.0f / 4096.0f);
    __syncthreads();

    // Hidden layer: warp w computes units w*8 .. w*8+7.
#pragma unroll
    for (int si = 0; si < 8; ++si) {
        const int u = w * 8 + si;
        const float4* wrow = reinterpret_cast<const float4*>(w1 + u * C);
        const float4* pr = reinterpret_cast<const float4*>(sp);
        float acc = 0.0f;
#pragma unroll
        for (int j = 0; j < 2; ++j) {
            float4 wv = wrow[lane + j * 32];
            float4 pv = pr[lane + j * 32];
            acc += wv.x * pv.x + wv.y * pv.y + wv.z * pv.z + wv.w * pv.w;
        }
#pragma unroll
        for (int o = 16; o; o >>= 1) acc += __shfl_xor_sync(0xFFFFFFFFu, acc, o);
        if (lane == 0) sh_[u] = fmaxf(acc + b1[u], 0.0f);
    }
    __syncthreads();

    // Output layer: thread t = channel c.
    const int c = t;
    float v = b2[c];
    const float4* w2r = reinterpret_cast<const float4*>(w2 + c * CS);
    const float4* hr = reinterpret_cast<const float4*>(sh_);
#pragma unroll
    for (int j = 0; j < 16; ++j) {
        float4 wv = w2r[j];
        float4 hv = hr[j];
        v += wv.x * hv.x + wv.y * hv.y + wv.z * hv.z + wv.w * hv.w;
    }
    const float sc = __saturatef(v / 6.0f + 0.5f);
    const int idx = b * C + c;
    g_scale[idx] = sc;
    float pmn = sc * g_min[idx];   // scale >= 0
    float pmx = sc * g_max[idx];
#pragma unroll
    for (int o = 16; o; o >>= 1) {
        pmn = fminf(pmn, __shfl_xor_sync(0xFFFFFFFFu, pmn, o));
        pmx = fmaxf(pmx, __shfl_xor_sync(0xFFFFFFFFu, pmx, o));
    }
    if (lane == 0) { rmn[w] = pmn; rmx[w] = pmx; }
    __syncthreads();
    if (t == 0) {
        float a = rmn[0], m = rmx[0];
#pragma unroll
        for (int i = 1; i < 8; ++i) { a = fminf(a, rmn[i]); m = fmaxf(m, rmx[i]); }
        g_smin[b] = a;
        g_smax[b] = m;
    }
}

// ---------------------------------------------------------------------------
// Kernel 3: fused cluster-EMA params + scale + fake-quant.
// PDL-dependent on se: prefetch x (input, safe) pre-wait, params post-wait.
// Per-warp redundant params (no sync, no smem). REVERSED block order; stores
// evict-first (best measured).
// ---------------------------------------------------------------------------
__device__ __forceinline__ float quant_one(float xv, float m1, float zz,
                                           float ss, float c2) {
    float y = __fmaf_rn(xv, m1, zz);
    y = fminf(fmaxf(y, 0.0f), 255.0f);
    // round-to-nearest-even via magic add, y in [0,255]
    float q = __fadd_rn(__fadd_rn(y, 12582912.0f), -12582912.0f);
    return __fmaf_rn(q, ss, c2);
}

__global__ __launch_bounds__(256) void quant_kernel(const float* __restrict__ x,
                                                    const float* __restrict__ ar,
                                                    const int* __restrict__ cl,
                                                    float* __restrict__ out) {
    const int bc = (BC - 1) - blockIdx.x;   // reverse order for L2 reuse
    const int b = bc >> 8;
    const int t = threadIdx.x;
    const int lane = t & 31;

    // ---- pre-wait: prefetch pure inputs ----
    const float4* px = reinterpret_cast<const float4*>(x) + (size_t)bc * 1024;
    float4 v0 = px[t];
    float4 v1 = px[t + 256];
    float4 v2 = px[t + 512];
    float4 v3 = px[t + 768];
    const int k = __ldg(&cl[b]);
    const int lk0 = __ldg(&cl[lane]);
    const int lk1 = __ldg(&cl[lane + 32]);
    const float ar0 = __ldg(&ar[2 * k]);
    const float ar1 = __ldg(&ar[2 * k + 1]);

    asm volatile("griddepcontrol.wait;" ::: "memory");

    // ---- per-warp redundant param computation (no cross-warp sync) ----
    float cmn = 3.4028235e38f, cmx = -3.4028235e38f;
    if (lk0 == k) {
        cmn = fminf(cmn, g_smin[lane]);
        cmx = fmaxf(cmx, g_smax[lane]);
    }
    if (lk1 == k) {
        cmn = fminf(cmn, g_smin[lane + 32]);
        cmx = fmaxf(cmx, g_smax[lane + 32]);
    }
#pragma unroll
    for (int o = 16; o; o >>= 1) {
        cmn = fminf(cmn, __shfl_xor_sync(0xFFFFFFFFu, cmn, o));
        cmx = fmaxf(cmx, __shfl_xor_sync(0xFFFFFFFFu, cmx, o));
    }
    const float nmn = ar0 * 0.995f + cmn * (1.0f - 0.995f);
    const float nmx = ar1 * 0.995f + cmx * (1.0f - 0.995f);
    const float ss = (nmx - nmn) / 255.0f;
    const float zz = -rintf(nmn / ss);
    const float c2 = -zz * ss;          // (q - z)*s = fma(q, s, -z*s)
    const float m1 = g_scale[bc] / ss;  // scale / s  (per channel)

    // ---- streaming fake-quant ----
    float4* po = reinterpret_cast<float4*>(out) + (size_t)bc * 1024;
    float4 o0, o1, o2, o3;
    o0.x = quant_one(v0.x, m1, zz, ss, c2); o0.y = quant_one(v0.y, m1, zz, ss, c2);
    o0.z = quant_one(v0.z, m1, zz, ss, c2); o0.w = quant_one(v0.w, m1, zz, ss, c2);
    o1.x = quant_one(v1.x, m1, zz, ss, c2); o1.y = quant_one(v1.y, m1, zz, ss, c2);
    o1.z = quant_one(v1.z, m1, zz, ss, c2); o1.w = quant_one(v1.w, m1, zz, ss, c2);
    o2.x = quant_one(v2.x, m1, zz, ss, c2); o2.y = quant_one(v2.y, m1, zz, ss, c2);
    o2.z = quant_one(v2.z, m1, zz, ss, c2); o2.w = quant_one(v2.w, m1, zz, ss, c2);
    o3.x = quant_one(v3.x, m1, zz, ss, c2); o3.y = quant_one(v3.y, m1, zz, ss, c2);
    o3.z = quant_one(v3.z, m1, zz, ss, c2); o3.w = quant_one(v3.w, m1, zz, ss, c2);
    __stcs(&po[t], o0);
    __stcs(&po[t + 256], o1);
    __stcs(&po[t + 512], o2);
    __stcs(&po[t + 768], o3);
}

extern "C" void kernel_launch(void* const* d_in, const int* in_sizes, int n_in,
                              void* d_out, int out_size) {
    (void)in_sizes; (void)n_in; (void)out_size;
    const float* x  = (const float*)d_in[0];
    const float* w1 = (const float*)d_in[1];
    const float* b1 = (const float*)d_in[2];
    const float* w2 = (const float*)d_in[3];
    const float* b2 = (const float*)d_in[4];
    const float* ar = (const float*)d_in[5];
    const int*   cl = (const int*)d_in[6];
    float* out = (float*)d_out;

    reduce_kernel<<<BC / 8, 256>>>(x);
    se_kernel<<<B, 256>>>(w1, b1, w2, b2);   // plain boundary after reduce

    cudaLaunchAttribute attr[1];
    attr[0].id = cudaLaunchAttributeProgrammaticStreamSerialization;
    attr[0].val.programmaticStreamSerializationAllowed = 1;

    cudaLaunchConfig_t cfg = {};
    cfg.gridDim = dim3(BC, 1, 1);
    cfg.blockDim = dim3(256, 1, 1);
    cfg.dynamicSmemBytes = 0;
    cfg.stream = 0;
    cfg.attrs = attr;
    cfg.numAttrs = 1;
    cudaLaunchKernelEx(&cfg, quant_kernel, x, ar, cl, out);
}

// round 15
// speedup vs baseline: 1.0521x; 1.0521x over previous
#include <cuda_runtime.h>
#include <cstdint>

#define B 64
#define C 256
#define CS 64
#define NC 8
#define BC (B * C)   // 16384

// Scratch (device globals: no allocation allowed)
__device__ float g_sum[BC];
__device__ float g_min[BC];
__device__ float g_max[BC];
__device__ float g_scale[BC];
__device__ float g_smin[B];
__device__ float g_smax[B];

// ---------------------------------------------------------------------------
// Kernel 1: per-(b,c) sum / min / max over 4096 spatial elements.
// One WARP per (b,c) row; 2048 blocks x 256 threads. Plain launch boundary
// after it (PDL here measurably steals its DRAM bandwidth - R6).
// ---------------------------------------------------------------------------
__global__ __launch_bounds__(256) void reduce_kernel(const float* __restrict__ x) {
    const int w = threadIdx.x >> 5;
    const int lane = threadIdx.x & 31;
    const int bc = (blockIdx.x << 3) + w;
    const float4* p = reinterpret_cast<const float4*>(x) + (size_t)bc * 1024;

    float s = 0.0f, mn = 3.4028235e38f, mx = -3.4028235e38f;
#pragma unroll 8
    for (int k = 0; k < 32; ++k) {
        float4 v = __ldcg(&p[lane + (k << 5)]);
        s += (v.x + v.y) + (v.z + v.w);
        mn = fminf(mn, fminf(fminf(v.x, v.y), fminf(v.z, v.w)));
        mx = fmaxf(mx, fmaxf(fmaxf(v.x, v.y), fmaxf(v.z, v.w)));
    }
#pragma unroll
    for (int o = 16; o; o >>= 1) {
        s += __shfl_xor_sync(0xFFFFFFFFu, s, o);
        mn = fminf(mn, __shfl_xor_sync(0xFFFFFFFFu, mn, o));
        mx = fmaxf(mx, __shfl_xor_sync(0xFFFFFFFFu, mx, o));
    }
    if (lane == 0) {
        g_sum[bc] = s;
        g_min[bc] = mn;
        g_max[bc] = mx;
    }
}

// ---------------------------------------------------------------------------
// Kernel 2: per-sample SE MLP + scale + per-sample min/max of (scale * x).
// 64 blocks x 256 threads. Triggers dependent (quant) launch at ENTRY:
// quant's first wave prefetches x during se's ~3us runtime (84 idle SMs).
// ---------------------------------------------------------------------------
__global__ __launch_bounds__(256) void se_kernel(const float* __restrict__ w1,
                                                 const float* __restrict__ b1,
                                                 const float* __restrict__ w2,
                                                 const float* __restrict__ b2) {
    asm volatile("griddepcontrol.launch_dependents;" ::: "memory");
    const int b = blockIdx.x;
    const int t = threadIdx.x;
    const int w = t >> 5, lane = t & 31;

    __shared__ __align__(16) float sp[C];
    __shared__ __align__(16) float sh_[CS];
    __shared__ float rmn[8], rmx[8];

    sp[t] = g_sum[b * C + t] * (1.0f / 4096.0f);
    __syncthreads();

    // Hidden layer: warp w computes units w*8 .. w*8+7.
#pragma unroll
    for (int si = 0; si < 8; ++si) {
        const int u = w * 8 + si;
        const float4* wrow = reinterpret_cast<const float4*>(w1 + u * C);
        const float4* pr = reinterpret_cast<const float4*>(sp);
        float acc = 0.0f;
#pragma unroll
        for (int j = 0; j < 2; ++j) {
            float4 wv = wrow[lane + j * 32];
            float4 pv = pr[lane + j * 32];
            acc += wv.x * pv.x + wv.y * pv.y + wv.z * pv.z + wv.w * pv.w;
        }
#pragma unroll
        for (int o = 16; o; o >>= 1) acc += __shfl_xor_sync(0xFFFFFFFFu, acc, o);
        if (lane == 0) sh_[u] = fmaxf(acc + b1[u], 0.0f);
    }
    __syncthreads();

    // Output layer: thread t = channel c.
    const int c = t;
    float v = b2[c];
    const float4* w2r = reinterpret_cast<const float4*>(w2 + c * CS);
    const float4* hr = reinterpret_cast<const float4*>(sh_);
#pragma unroll
    for (int j = 0; j < 16; ++j) {
        float4 wv = w2r[j];
        float4 hv = hr[j];
        v += wv.x * hv.x + wv.y * hv.y + wv.z * hv.z + wv.w * hv.w;
    }
    const float sc = __saturatef(v / 6.0f + 0.5f);
    const int idx = b * C + c;
    g_scale[idx] = sc;
    float pmn = sc * g_min[idx];   // scale >= 0
    float pmx = sc * g_max[idx];
#pragma unroll
    for (int o = 16; o; o >>= 1) {
        pmn = fminf(pmn, __shfl_xor_sync(0xFFFFFFFFu, pmn, o));
        pmx = fmaxf(pmx, __shfl_xor_sync(0xFFFFFFFFu, pmx, o));
    }
    if (lane == 0) { rmn[w] = pmn; rmx[w] = pmx; }
    __syncthreads();
    if (t == 0) {
        float a = rmn[0], m = rmx[0];
#pragma unroll
        for (int i = 1; i < 8; ++i) { a = fminf(a, rmn[i]); m = fmaxf(m, rmx[i]); }
        g_smin[b] = a;
        g_smax[b] = m;
    }
}

// ---------------------------------------------------------------------------
// Kernel 3: fused cluster-EMA params + scale + fake-quant.
// PDL-dependent on se: prefetch x (input, safe) pre-wait, params post-wait.
// Per-warp redundant params (no sync, no smem). REVERSED block order; stores
// evict-first (best measured).
// ---------------------------------------------------------------------------
__device__ __forceinline__ float quant_one(float xv, float m1, float zz,
                                           float ss, float c2) {
    float y = __fmaf_rn(xv, m1, zz);
    y = fminf(fmaxf(y, 0.0f), 255.0f);
    // round-to-nearest-even via magic add, y in [0,255]
    float q = __fadd_rn(__fadd_rn(y, 12582912.0f), -12582912.0f);
    return __fmaf_rn(q, ss, c2);
}

__global__ __launch_bounds__(256) void quant_kernel(const float* __restrict__ x,
                                                    const float* __restrict__ ar,
                                                    const int* __restrict__ cl,
                                                    float* __restrict__ out) {
    const int bc = (BC - 1) - blockIdx.x;   // reverse order for L2 reuse
    const int b = bc >> 8;
    const int t = threadIdx.x;
    const int lane = t & 31;

    // ---- pre-wait: prefetch pure inputs ----
    const float4* px = reinterpret_cast<const float4*>(x) + (size_t)bc * 1024;
    float4 v0 = px[t];
    float4 v1 = px[t + 256];
    float4 v2 = px[t + 512];
    float4 v3 = px[t + 768];
    const int k = __ldg(&cl[b]);
    const int lk0 = __ldg(&cl[lane]);
    const int lk1 = __ldg(&cl[lane + 32]);
    const float ar0 = __ldg(&ar[2 * k]);
    const float ar1 = __ldg(&ar[2 * k + 1]);

    asm volatile("griddepcontrol.wait;" ::: "memory");

    // ---- per-warp redundant param computation (no cross-warp sync) ----
    float cmn = 3.4028235e38f, cmx = -3.4028235e38f;
    if (lk0 == k) {
        cmn = fminf(cmn, g_smin[lane]);
        cmx = fmaxf(cmx, g_smax[lane]);
    }
    if (lk1 == k) {
        cmn = fminf(cmn, g_smin[lane + 32]);
        cmx = fmaxf(cmx, g_smax[lane + 32]);
    }
#pragma unroll
    for (int o = 16; o; o >>= 1) {
        cmn = fminf(cmn, __shfl_xor_sync(0xFFFFFFFFu, cmn, o));
        cmx = fmaxf(cmx, __shfl_xor_sync(0xFFFFFFFFu, cmx, o));
    }
    const float nmn = ar0 * 0.995f + cmn * (1.0f - 0.995f);
    const float nmx = ar1 * 0.995f + cmx * (1.0f - 0.995f);
    const float ss = (nmx - nmn) / 255.0f;
    const float zz = -rintf(nmn / ss);
    const float c2 = -zz * ss;          // (q - z)*s = fma(q, s, -z*s)
    const float m1 = g_scale[bc] / ss;  // scale / s  (per channel)

    // ---- streaming fake-quant ----
    float4* po = reinterpret_cast<float4*>(out) + (size_t)bc * 1024;
    float4 o0, o1, o2, o3;
    o0.x = quant_one(v0.x, m1, zz, ss, c2); o0.y = quant_one(v0.y, m1, zz, ss, c2);
    o0.z = quant_one(v0.z, m1, zz, ss, c2); o0.w = quant_one(v0.w, m1, zz, ss, c2);
    o1.x = quant_one(v1.x, m1, zz, ss, c2); o1.y = quant_one(v1.y, m1, zz, ss, c2);
    o1.z = quant_one(v1.z, m1, zz, ss, c2); o1.w = quant_one(v1.w, m1, zz, ss, c2);
    o2.x = quant_one(v2.x, m1, zz, ss, c2); o2.y = quant_one(v2.y, m1, zz, ss, c2);
    o2.z = quant_one(v2.z, m1, zz, ss, c2); o2.w = quant_one(v2.w, m1, zz, ss, c2);
    o3.x = quant_one(v3.x, m1, zz, ss, c2); o3.y = quant_one(v3.y, m1, zz, ss, c2);
    o3.z = quant_one(v3.z, m1, zz, ss, c2); o3.w = quant_one(v3.w, m1, zz, ss, c2);
    __stcs(&po[t], o0);
    __stcs(&po[t + 256], o1);
    __stcs(&po[t + 512], o2);
    __stcs(&po[t + 768], o3);
}

extern "C" void kernel_launch(void* const* d_in, const int* in_sizes, int n_in,
                              void* d_out, int out_size) {
    (void)in_sizes; (void)n_in; (void)out_size;
    const float* x  = (const float*)d_in[0];
    const float* w1 = (const float*)d_in[1];
    const float* b1 = (const float*)d_in[2];
    const float* w2 = (const float*)d_in[3];
    const float* b2 = (const float*)d_in[4];
    const float* ar = (const float*)d_in[5];
    const int*   cl = (const int*)d_in[6];
    float* out = (float*)d_out;

    reduce_kernel<<<BC / 8, 256>>>(x);
    se_kernel<<<B, 256>>>(w1, b1, w2, b2);   // plain boundary after reduce

    cudaLaunchAttribute attr[1];
    attr[0].id = cudaLaunchAttributeProgrammaticStreamSerialization;
    attr[0].val.programmaticStreamSerializationAllowed = 1;

    cudaLaunchConfig_t cfg = {};
    cfg.gridDim = dim3(BC, 1, 1);
    cfg.blockDim = dim3(256, 1, 1);
    cfg.dynamicSmemBytes = 0;
    cfg.stream = 0;
    cfg.attrs = attr;
    cfg.numAttrs = 1;
    cudaLaunchKernelEx(&cfg, quant_kernel, x, ar, cl, out);
}